// round 1
// baseline (speedup 1.0000x reference)
#include <cuda_runtime.h>
#include <math.h>

#define B_ 16
#define C_ 128
#define T_ 25
#define J_ 25
#define N_ 25
#define F_ 256
#define NB_S (B_*T_)   // 400 spatial blocks
#define NB_T (B_*J_)   // 400 temporal blocks

// Precomputed device-global scratch (no allocation allowed)
__device__ float g_w1s[C_], g_w2s[C_], g_w1t[C_], g_w2t[C_];
__device__ float g_sumw1s, g_sumw2s;
__device__ float g_posd1[T_], g_posd2[T_];
__device__ float g_pos[T_ * C_];

// ---------------------------------------------------------------------------
// Kernel 1: sinusoid table in fp64 (matches numpy float64 table -> f32 cast).
// Spread over 100 blocks x 32 threads because fp64 sin/cos/pow are slow.
// ---------------------------------------------------------------------------
__global__ void pos_table_kernel() {
    int idx = blockIdx.x * blockDim.x + threadIdx.x;
    if (idx >= T_ * C_) return;
    int t = idx / C_;
    int h = idx % C_;
    double expo = (double)(h >> 1) * (2.0 / (double)C_);
    double denom = pow(10000.0, expo);
    double angle = (double)t / denom;
    double v = (h & 1) ? cos(angle) : sin(angle);
    g_pos[idx] = (float)v;   // reference casts f64 table to f32, THEN *1000
}

// ---------------------------------------------------------------------------
// Kernel 2: w1 = W @ a[:F], w2 = W @ a[F:], sums, and pos-dot constants.
// ---------------------------------------------------------------------------
__global__ void weights_kernel(const float* __restrict__ Ws,
                               const float* __restrict__ as_,
                               const float* __restrict__ Wt,
                               const float* __restrict__ at_) {
    __shared__ float sw1s[C_], sw2s[C_], sw1t[C_], sw2t[C_];
    int c = threadIdx.x;   // 128 threads
    {
        float a1 = 0.f, a2 = 0.f, b1 = 0.f, b2 = 0.f;
        const float* wsrow = Ws + c * F_;
        const float* wtrow = Wt + c * F_;
        #pragma unroll 4
        for (int f = 0; f < F_; ++f) {
            float ws = wsrow[f], wt = wtrow[f];
            a1 = fmaf(ws, as_[f],       a1);
            a2 = fmaf(ws, as_[F_ + f],  a2);
            b1 = fmaf(wt, at_[f],       b1);
            b2 = fmaf(wt, at_[F_ + f],  b2);
        }
        g_w1s[c] = a1; g_w2s[c] = a2; g_w1t[c] = b1; g_w2t[c] = b2;
        sw1s[c] = a1; sw2s[c] = a2; sw1t[c] = b1; sw2t[c] = b2;
    }
    __syncthreads();
    if (c == 0) {
        float s1 = 0.f, s2 = 0.f;
        for (int i = 0; i < C_; ++i) { s1 += sw1s[i]; s2 += sw2s[i]; }
        g_sumw1s = s1; g_sumw2s = s2;
    }
    if (c < T_) {
        // Kahan-compensated dot of (pos[t]*1000) with w1t / w2t
        float sum1 = 0.f, comp1 = 0.f, sum2 = 0.f, comp2 = 0.f;
        for (int h = 0; h < C_; ++h) {
            float pv = g_pos[c * C_ + h] * 1000.0f;
            float t1 = pv * sw1t[h];
            float y1 = t1 - comp1;
            float z1 = sum1 + y1;
            comp1 = (z1 - sum1) - y1;
            sum1 = z1;
            float t2 = pv * sw2t[h];
            float y2 = t2 - comp2;
            float z2 = sum2 + y2;
            comp2 = (z2 - sum2) - y2;
            sum2 = z2;
        }
        g_posd1[c] = sum1; g_posd2[c] = sum2;
    }
}

// ---------------------------------------------------------------------------
// Kernel 3: fused GAT logits + leaky-relu + double softmax, both branches.
// Blocks [0,400): spatial (b,t).  Blocks [400,800): temporal (b,j).
// ---------------------------------------------------------------------------
__global__ void __launch_bounds__(128) stgat_kernel(const float* __restrict__ src,
                                                    float* __restrict__ out) {
    __shared__ float xs[N_][C_ + 1];      // +1 pad: conflict-free column access
    __shared__ float s1[N_], s2[N_];
    __shared__ float ee[N_ * N_];
    __shared__ float w1[C_], w2[C_];

    int bid = blockIdx.x;
    int tid = threadIdx.x;
    bool spatial = bid < NB_S;

    if (spatial) { w1[tid] = g_w1s[tid]; w2[tid] = g_w2s[tid]; }
    else         { w1[tid] = g_w1t[tid]; w2[tid] = g_w2t[tid]; }

    const float* base;
    int stride_n;
    if (spatial) {
        int b = bid / T_, t = bid % T_;
        base = src + (size_t)b * (C_ * T_ * J_) + t * J_;  // + c*625 + j
        stride_n = 1;
    } else {
        int bj = bid - NB_S;
        int b = bj / J_, j = bj % J_;
        base = src + (size_t)b * (C_ * T_ * J_) + j;       // + c*625 + t*25
        stride_n = J_;
    }

    // Load the 25x128 slice into smem: xs[node][channel]
    for (int i = tid; i < N_ * C_; i += 128) {
        int c = i / N_, n = i % N_;
        xs[n][c] = __ldg(base + c * (T_ * J_) + n * stride_n);
    }
    __syncthreads();

    // Per-node scalars: s1[n] = x[n]·w1 (+PE term), s2[n] = x[n]·w2 (+PE term)
    if (tid < N_) {
        float acc1 = 0.f, acc2 = 0.f, ss = 0.f;
        #pragma unroll 8
        for (int c = 0; c < C_; ++c) {
            float xv = xs[tid][c];
            acc1 = fmaf(xv, w1[c], acc1);
            acc2 = fmaf(xv, w2[c], acc2);
            float d = xv - xs[8][c];
            ss = fmaf(d, d, ss);
        }
        if (spatial) {
            // c = ||(x - x8)/1000||;  x_pe = x + exp(-c)  (added to every channel)
            float delta = expf(-sqrtf(ss) * 0.001f);
            s1[tid] = fmaf(delta, g_sumw1s, acc1);
            s2[tid] = fmaf(delta, g_sumw2s, acc2);
        } else {
            s1[tid] = acc1 + g_posd1[tid];
            s2[tid] = acc2 + g_posd2[tid];
        }
    }
    __syncthreads();

    // Logits via the reference's axis-1 concat + reshape index arithmetic:
    // e[p,q] uses cat rows k1=2pN+2q, k2=k1+1;
    // cat[k] = (k < N^2) ? h[k/N] (hi) : h[(k-N^2)%N] (hj)
    for (int i = tid; i < N_ * N_; i += 128) {
        int p = i / N_, q = i % N_;
        int k1 = 2 * p * N_ + 2 * q;
        int k2 = k1 + 1;
        int n1 = (k1 < N_ * N_) ? (k1 / N_) : ((k1 - N_ * N_) % N_);
        int n2 = (k2 < N_ * N_) ? (k2 / N_) : ((k2 - N_ * N_) % N_);
        float v = s1[n1] + s2[n2];
        ee[i] = (v >= 0.f) ? v : 0.2f * v;    // leaky_relu, slope 0.2
    }
    __syncthreads();

    // Double softmax over p (axis 1 of (Bn,N,N), then axis -2 after reshape
    // = same axis). One column q per thread; 25 values live in registers.
    if (tid < N_) {
        int q = tid;
        float v[N_];
        float m = -3.402823466e38f;
        #pragma unroll
        for (int p = 0; p < N_; ++p) { v[p] = ee[p * N_ + q]; m = fmaxf(m, v[p]); }
        float s = 0.f;
        #pragma unroll
        for (int p = 0; p < N_; ++p) { v[p] = expf(v[p] - m); s += v[p]; }
        float inv = 1.f / s;
        float m2 = -3.402823466e38f;
        #pragma unroll
        for (int p = 0; p < N_; ++p) { v[p] *= inv; m2 = fmaxf(m2, v[p]); }
        float s2v = 0.f;
        #pragma unroll
        for (int p = 0; p < N_; ++p) { v[p] = expf(v[p] - m2); s2v += v[p]; }
        float inv2 = 1.f / s2v;
        // spatial blocks write [0, 250000); temporal blocks [250000, 500000).
        // Both collapse to out + bid*625.
        float* o = out + (size_t)bid * (N_ * N_);
        #pragma unroll
        for (int p = 0; p < N_; ++p) o[p * N_ + q] = v[p] * inv2;
    }
}

extern "C" void kernel_launch(void* const* d_in, const int* in_sizes, int n_in,
                              void* d_out, int out_size) {
    const float* src = (const float*)d_in[0];
    const float* Ws  = (const float*)d_in[1];
    const float* as_ = (const float*)d_in[2];
    const float* Wt  = (const float*)d_in[3];
    const float* at_ = (const float*)d_in[4];
    float* out = (float*)d_out;

    pos_table_kernel<<<100, 32>>>();
    weights_kernel<<<1, 128>>>(Ws, as_, Wt, at_);
    stgat_kernel<<<NB_S + NB_T, 128>>>(src, out);
}

// round 2
// speedup vs baseline: 2.5405x; 2.5405x over previous
#include <cuda_runtime.h>
#include <math.h>

#define B_ 16
#define C_ 128
#define T_ 25
#define J_ 25
#define N_ 25
#define F_ 256
#define NB_S (B_*T_)   // 400 spatial blocks
#define NB_T (B_*J_)   // 400 temporal blocks

// Precomputed device-global scratch (no allocation allowed)
__device__ float g_w1s[C_], g_w2s[C_], g_w1t[C_], g_w2t[C_];
__device__ float g_sumw1s, g_sumw2s;
__device__ float g_posd1[T_], g_posd2[T_];
__device__ float g_pos[T_ * C_];

// ---------------------------------------------------------------------------
// PRE1: blocks 0..15  -> w vectors (warp-per-row, coalesced, butterfly reduce)
//       blocks 16..40 -> fp64 sinusoid table (1 entry / thread)
// The two roles are independent; they run concurrently in one launch.
// ---------------------------------------------------------------------------
__global__ void __launch_bounds__(128) pre1_kernel(const float* __restrict__ Ws,
                                                   const float* __restrict__ as_,
                                                   const float* __restrict__ Wt,
                                                   const float* __restrict__ at_) {
    int bi = blockIdx.x;
    int tid = threadIdx.x;

    if (bi < 16) {
        // blocks 0-7: Ws rows [bi*16, bi*16+16); blocks 8-15: Wt rows likewise.
        bool is_s = bi < 8;
        const float* W = is_s ? Ws : Wt;
        const float* a = is_s ? as_ : at_;
        float* o1 = is_s ? g_w1s : g_w1t;
        float* o2 = is_s ? g_w2s : g_w2t;
        int row0 = (bi & 7) * 16;

        int wid = tid >> 5;
        int lane = tid & 31;

        // Preload a-coefficients for this lane (shared across the 4 rows)
        float a1v[8], a2v[8];
        #pragma unroll
        for (int u = 0; u < 8; ++u) {
            a1v[u] = __ldg(a + lane + 32 * u);
            a2v[u] = __ldg(a + F_ + lane + 32 * u);
        }

        #pragma unroll
        for (int k = 0; k < 4; ++k) {
            int row = row0 + wid * 4 + k;
            const float* Wrow = W + (size_t)row * F_;
            float acc1 = 0.f, acc2 = 0.f;
            #pragma unroll
            for (int u = 0; u < 8; ++u) {
                float wv = __ldg(Wrow + lane + 32 * u);
                acc1 = fmaf(wv, a1v[u], acc1);
                acc2 = fmaf(wv, a2v[u], acc2);
            }
            #pragma unroll
            for (int off = 16; off > 0; off >>= 1) {
                acc1 += __shfl_xor_sync(0xffffffffu, acc1, off);
                acc2 += __shfl_xor_sync(0xffffffffu, acc2, off);
            }
            if (lane == 0) { o1[row] = acc1; o2[row] = acc2; }
        }
    } else {
        // pos table: block (bi-16) = time t, thread = channel h. fp64 to match
        // numpy's float64 table (cast to f32 BEFORE the *1000 in the caller).
        int t = bi - 16;
        int h = tid;
        double expo = (double)(h >> 1) * (2.0 / (double)C_);
        double denom = pow(10000.0, expo);
        double angle = (double)t / denom;
        double v = (h & 1) ? cos(angle) : sin(angle);
        g_pos[t * C_ + h] = (float)v;
    }
}

// ---------------------------------------------------------------------------
// PRE2 (1 block): constants that need all w rows / the pos table.
//   warp 0 lanes <25 : Kahan dot  posd[t] = (pos[t]*1000) . w{1,2}t
//   warp 1           : sumw1s/sumw2s via lane-parallel + butterfly reduce
// ---------------------------------------------------------------------------
__global__ void __launch_bounds__(128) pre2_kernel() {
    int tid = threadIdx.x;
    if (tid < T_) {
        float sum1 = 0.f, comp1 = 0.f, sum2 = 0.f, comp2 = 0.f;
        const float* prow = g_pos + tid * C_;
        for (int h = 0; h < C_; ++h) {
            float pv = prow[h] * 1000.0f;
            float t1 = pv * g_w1t[h];
            float y1 = t1 - comp1;
            float z1 = sum1 + y1;
            comp1 = (z1 - sum1) - y1;
            sum1 = z1;
            float t2 = pv * g_w2t[h];
            float y2 = t2 - comp2;
            float z2 = sum2 + y2;
            comp2 = (z2 - sum2) - y2;
            sum2 = z2;
        }
        g_posd1[tid] = sum1; g_posd2[tid] = sum2;
    } else if (tid >= 32 && tid < 64) {
        int lane = tid - 32;
        float s1 = g_w1s[lane] + g_w1s[lane + 32] + g_w1s[lane + 64] + g_w1s[lane + 96];
        float s2 = g_w2s[lane] + g_w2s[lane + 32] + g_w2s[lane + 64] + g_w2s[lane + 96];
        #pragma unroll
        for (int off = 16; off > 0; off >>= 1) {
            s1 += __shfl_xor_sync(0xffffffffu, s1, off);
            s2 += __shfl_xor_sync(0xffffffffu, s2, off);
        }
        if (lane == 0) { g_sumw1s = s1; g_sumw2s = s2; }
    }
}

// ---------------------------------------------------------------------------
// Kernel 3: fused GAT logits + leaky-relu + double softmax, both branches.
// Blocks [0,400): spatial (b,t).  Blocks [400,800): temporal (b,j).
// ---------------------------------------------------------------------------
__global__ void __launch_bounds__(128) stgat_kernel(const float* __restrict__ src,
                                                    float* __restrict__ out) {
    __shared__ float xs[N_][C_ + 1];      // +1 pad: conflict-free column access
    __shared__ float s1[N_], s2[N_];
    __shared__ float ee[N_ * N_];
    __shared__ float w1[C_], w2[C_];

    int bid = blockIdx.x;
    int tid = threadIdx.x;
    bool spatial = bid < NB_S;

    if (spatial) { w1[tid] = g_w1s[tid]; w2[tid] = g_w2s[tid]; }
    else         { w1[tid] = g_w1t[tid]; w2[tid] = g_w2t[tid]; }

    const float* base;
    int stride_n;
    if (spatial) {
        int b = bid / T_, t = bid % T_;
        base = src + (size_t)b * (C_ * T_ * J_) + t * J_;  // + c*625 + j
        stride_n = 1;
    } else {
        int bj = bid - NB_S;
        int b = bj / J_, j = bj % J_;
        base = src + (size_t)b * (C_ * T_ * J_) + j;       // + c*625 + t*25
        stride_n = J_;
    }

    // Load the 25x128 slice into smem: xs[node][channel]
    for (int i = tid; i < N_ * C_; i += 128) {
        int c = i / N_, n = i % N_;
        xs[n][c] = __ldg(base + c * (T_ * J_) + n * stride_n);
    }
    __syncthreads();

    // Per-node scalars: s1[n] = x[n]·w1 (+PE term), s2[n] = x[n]·w2 (+PE term)
    if (tid < N_) {
        float acc1 = 0.f, acc2 = 0.f, ss = 0.f;
        #pragma unroll 8
        for (int c = 0; c < C_; ++c) {
            float xv = xs[tid][c];
            acc1 = fmaf(xv, w1[c], acc1);
            acc2 = fmaf(xv, w2[c], acc2);
            float d = xv - xs[8][c];
            ss = fmaf(d, d, ss);
        }
        if (spatial) {
            // c = ||(x - x8)/1000||;  x_pe = x + exp(-c)  (added to every channel)
            float delta = expf(-sqrtf(ss) * 0.001f);
            s1[tid] = fmaf(delta, g_sumw1s, acc1);
            s2[tid] = fmaf(delta, g_sumw2s, acc2);
        } else {
            s1[tid] = acc1 + g_posd1[tid];
            s2[tid] = acc2 + g_posd2[tid];
        }
    }
    __syncthreads();

    // Logits via the reference's axis-1 concat + reshape index arithmetic:
    // e[p,q] uses cat rows k1=2pN+2q, k2=k1+1;
    // cat[k] = (k < N^2) ? h[k/N] (hi) : h[(k-N^2)%N] (hj)
    for (int i = tid; i < N_ * N_; i += 128) {
        int p = i / N_, q = i % N_;
        int k1 = 2 * p * N_ + 2 * q;
        int k2 = k1 + 1;
        int n1 = (k1 < N_ * N_) ? (k1 / N_) : ((k1 - N_ * N_) % N_);
        int n2 = (k2 < N_ * N_) ? (k2 / N_) : ((k2 - N_ * N_) % N_);
        float v = s1[n1] + s2[n2];
        ee[i] = (v >= 0.f) ? v : 0.2f * v;    // leaky_relu, slope 0.2
    }
    __syncthreads();

    // Double softmax over p. One column q per thread; 25 values in registers.
    if (tid < N_) {
        int q = tid;
        float v[N_];
        float m = -3.402823466e38f;
        #pragma unroll
        for (int p = 0; p < N_; ++p) { v[p] = ee[p * N_ + q]; m = fmaxf(m, v[p]); }
        float s = 0.f;
        #pragma unroll
        for (int p = 0; p < N_; ++p) { v[p] = expf(v[p] - m); s += v[p]; }
        float inv = 1.f / s;
        float m2 = -3.402823466e38f;
        #pragma unroll
        for (int p = 0; p < N_; ++p) { v[p] *= inv; m2 = fmaxf(m2, v[p]); }
        float s2v = 0.f;
        #pragma unroll
        for (int p = 0; p < N_; ++p) { v[p] = expf(v[p] - m2); s2v += v[p]; }
        float inv2 = 1.f / s2v;
        float* o = out + (size_t)bid * (N_ * N_);
        #pragma unroll
        for (int p = 0; p < N_; ++p) o[p * N_ + q] = v[p] * inv2;
    }
}

extern "C" void kernel_launch(void* const* d_in, const int* in_sizes, int n_in,
                              void* d_out, int out_size) {
    const float* src = (const float*)d_in[0];
    const float* Ws  = (const float*)d_in[1];
    const float* as_ = (const float*)d_in[2];
    const float* Wt  = (const float*)d_in[3];
    const float* at_ = (const float*)d_in[4];
    float* out = (float*)d_out;

    pre1_kernel<<<16 + T_, 128>>>(Ws, as_, Wt, at_);
    pre2_kernel<<<1, 128>>>();
    stgat_kernel<<<NB_S + NB_T, 128>>>(src, out);
}

// round 4
// speedup vs baseline: 3.2580x; 1.2824x over previous
#include <cuda_runtime.h>
#include <math.h>

#define B_ 16
#define C_ 128
#define T_ 25
#define J_ 25
#define N_ 25
#define F_ 256
#define NB_S (B_*T_)   // 400 spatial blocks
#define NB_T (B_*J_)   // 400 temporal blocks
#define XS_STRIDE 132  // floats per smem row (128 + 4 pad, float4 compatible)

// Precomputed device-global scratch (static __device__ arrays: allowed)
__device__ float g_w1s[C_], g_w2s[C_], g_w1t[C_], g_w2t[C_];
__device__ float g_posd1[T_], g_posd2[T_];
__device__ float g_pos[T_ * C_];
__device__ float4 g_srcT4[B_ * J_ * T_ * (C_ / 4)];   // srcT[b][j][t][c], 5.12 MB

// ---------------------------------------------------------------------------
// K1: blocks 0..15  -> w vectors (warp-per-row, coalesced, butterfly reduce)
//     blocks 16..40 -> fp64 sinusoid table, one sincos per (t, h/2) pair
// ---------------------------------------------------------------------------
__global__ void __launch_bounds__(128) pre1_kernel(const float* __restrict__ Ws,
                                                   const float* __restrict__ as_,
                                                   const float* __restrict__ Wt,
                                                   const float* __restrict__ at_) {
    int bi = blockIdx.x;
    int tid = threadIdx.x;

    if (bi < 16) {
        bool is_s = bi < 8;
        const float* W = is_s ? Ws : Wt;
        const float* a = is_s ? as_ : at_;
        float* o1 = is_s ? g_w1s : g_w1t;
        float* o2 = is_s ? g_w2s : g_w2t;
        int row0 = (bi & 7) * 16;

        int wid = tid >> 5;
        int lane = tid & 31;

        float a1v[8], a2v[8];
        #pragma unroll
        for (int u = 0; u < 8; ++u) {
            a1v[u] = __ldg(a + lane + 32 * u);
            a2v[u] = __ldg(a + F_ + lane + 32 * u);
        }

        #pragma unroll
        for (int k = 0; k < 4; ++k) {
            int row = row0 + wid * 4 + k;
            const float* Wrow = W + (size_t)row * F_;
            float acc1 = 0.f, acc2 = 0.f;
            #pragma unroll
            for (int u = 0; u < 8; ++u) {
                float wv = __ldg(Wrow + lane + 32 * u);
                acc1 = fmaf(wv, a1v[u], acc1);
                acc2 = fmaf(wv, a2v[u], acc2);
            }
            #pragma unroll
            for (int off = 16; off > 0; off >>= 1) {
                acc1 += __shfl_xor_sync(0xffffffffu, acc1, off);
                acc2 += __shfl_xor_sync(0xffffffffu, acc2, off);
            }
            if (lane == 0) { o1[row] = acc1; o2[row] = acc2; }
        }
    } else if (tid < C_ / 2) {
        // pos table: block = time t, thread = h/2. One double sincos per pair.
        // Matches numpy float64 table (cast to f32 before the later *1000).
        int t = bi - 16;
        int h2 = tid;                              // 0..63
        double expo = (double)h2 * (2.0 / (double)C_);
        double angle = (double)t / pow(10000.0, expo);
        double sv, cv;
        sincos(angle, &sv, &cv);
        g_pos[t * C_ + 2 * h2]     = (float)sv;    // even col: sin
        g_pos[t * C_ + 2 * h2 + 1] = (float)cv;    // odd  col: cos
    }
}

// ---------------------------------------------------------------------------
// K2: blocks 0..399: spatial attention for (b,t) + transposed staging write
//     block  400   : posd constants (fp64 tree dot of pos*1000 with w1t/w2t)
// ---------------------------------------------------------------------------
__global__ void __launch_bounds__(128) spatial_kernel(const float* __restrict__ src,
                                                      float* __restrict__ out) {
    int bid = blockIdx.x;
    int tid = threadIdx.x;
    int wid = tid >> 5;
    int lane = tid & 31;

    if (bid == NB_S) {
        // posd[t] = sum_c (f32(pos[t][c]) * 1000.0f) * w{1,2}t[c], in fp64.
        for (int t = wid; t < T_; t += 4) {
            double a1 = 0.0, a2 = 0.0;
            #pragma unroll
            for (int k = 0; k < 4; ++k) {
                int c = 4 * lane + k;
                float pv = g_pos[t * C_ + c] * 1000.0f;
                a1 += (double)pv * (double)g_w1t[c];
                a2 += (double)pv * (double)g_w2t[c];
            }
            #pragma unroll
            for (int off = 16; off > 0; off >>= 1) {
                a1 += __shfl_xor_sync(0xffffffffu, a1, off);
                a2 += __shfl_xor_sync(0xffffffffu, a2, off);
            }
            if (lane == 0) { g_posd1[t] = (float)a1; g_posd2[t] = (float)a2; }
        }
        return;
    }

    __shared__ float4 xs4[N_ * (XS_STRIDE / 4)];
    __shared__ float s1[N_], s2[N_];
    __shared__ float ee[N_ * N_];
    __shared__ float w1[C_], w2[C_];
    __shared__ float sumw1, sumw2;
    float* xs = (float*)xs4;

    int b = bid / T_, t = bid % T_;
    const float* base = src + (size_t)b * (C_ * T_ * J_) + t * J_;  // +c*625+j

    w1[tid] = g_w1s[tid];
    w2[tid] = g_w2s[tid];

    // gather x[j][c] (25-float contiguous runs along j)
    for (int i = tid; i < N_ * C_; i += 128) {
        int c = i / N_, n = i % N_;
        xs[n * XS_STRIDE + c] = __ldg(base + c * (T_ * J_) + n);
    }
    if (wid == 0) {   // sum of w vectors (for the spatial-PE scalar term)
        float v1 = w1[lane] + w1[lane + 32] + w1[lane + 64] + w1[lane + 96];
        float v2 = w2[lane] + w2[lane + 32] + w2[lane + 64] + w2[lane + 96];
        #pragma unroll
        for (int off = 16; off > 0; off >>= 1) {
            v1 += __shfl_xor_sync(0xffffffffu, v1, off);
            v2 += __shfl_xor_sync(0xffffffffu, v2, off);
        }
        if (lane == 0) { sumw1 = v1; sumw2 = v2; }
    }
    __syncthreads();

    // transposed staging write: srcT[b][j][t][c], coalesced 512B rows
    {
        float4* dst = g_srcT4 + ((size_t)b * J_) * (T_ * 32) + t * 32;
        for (int i = tid; i < N_ * 32; i += 128) {
            int j = i >> 5, c4 = i & 31;
            dst[(size_t)j * (T_ * 32) + c4] = xs4[j * (XS_STRIDE / 4) + c4];
        }
    }

    // warp-parallel per-node dots (+ PE distance to node 8)
    for (int n = wid; n < N_; n += 4) {
        float acc1 = 0.f, acc2 = 0.f, ss = 0.f;
        float4 xv4 = xs4[n * (XS_STRIDE / 4) + lane];
        float4 x84 = xs4[8 * (XS_STRIDE / 4) + lane];
        const float* xv = (const float*)&xv4;
        const float* x8 = (const float*)&x84;
        #pragma unroll
        for (int k = 0; k < 4; ++k) {
            int c = 4 * lane + k;
            acc1 = fmaf(xv[k], w1[c], acc1);
            acc2 = fmaf(xv[k], w2[c], acc2);
            float d = xv[k] - x8[k];
            ss = fmaf(d, d, ss);
        }
        #pragma unroll
        for (int off = 16; off > 0; off >>= 1) {
            acc1 += __shfl_xor_sync(0xffffffffu, acc1, off);
            acc2 += __shfl_xor_sync(0xffffffffu, acc2, off);
            ss   += __shfl_xor_sync(0xffffffffu, ss,   off);
        }
        if (lane == 0) {
            // c = ||(x - x8)/1000||; PE adds exp(-c) to every channel
            float delta = expf(-sqrtf(ss) * 0.001f);
            s1[n] = fmaf(delta, sumw1, acc1);
            s2[n] = fmaf(delta, sumw2, acc2);
        }
    }
    __syncthreads();

    // logits via reference's axis-1 concat index arithmetic + leaky relu
    for (int i = tid; i < N_ * N_; i += 128) {
        int p = i / N_, q = i % N_;
        int k1 = 2 * p * N_ + 2 * q;
        int k2 = k1 + 1;
        int n1 = (k1 < N_ * N_) ? (k1 / N_) : ((k1 - N_ * N_) % N_);
        int n2 = (k2 < N_ * N_) ? (k2 / N_) : ((k2 - N_ * N_) % N_);
        float v = s1[n1] + s2[n2];
        ee[i] = (v >= 0.f) ? v : 0.2f * v;
    }
    __syncthreads();

    // double softmax over p; one column q per thread
    if (tid < N_) {
        int q = tid;
        float v[N_];
        float m = -3.402823466e38f;
        #pragma unroll
        for (int p = 0; p < N_; ++p) { v[p] = ee[p * N_ + q]; m = fmaxf(m, v[p]); }
        float s = 0.f;
        #pragma unroll
        for (int p = 0; p < N_; ++p) { v[p] = expf(v[p] - m); s += v[p]; }
        float inv = 1.f / s;
        float m2 = -3.402823466e38f;
        #pragma unroll
        for (int p = 0; p < N_; ++p) { v[p] *= inv; m2 = fmaxf(m2, v[p]); }
        float s2v = 0.f;
        #pragma unroll
        for (int p = 0; p < N_; ++p) { v[p] = expf(v[p] - m2); s2v += v[p]; }
        float inv2 = 1.f / s2v;
        float* o = out + (size_t)bid * (N_ * N_);
        #pragma unroll
        for (int p = 0; p < N_; ++p) o[p * N_ + q] = v[p] * inv2;
    }
}

// ---------------------------------------------------------------------------
// K3: temporal attention for (b,j), reading the transposed staging tensor
//     with fully coalesced float4 loads.
// ---------------------------------------------------------------------------
__global__ void __launch_bounds__(128) temporal_kernel(float* __restrict__ out) {
    __shared__ float4 xs4[N_ * (XS_STRIDE / 4)];
    __shared__ float s1[N_], s2[N_];
    __shared__ float ee[N_ * N_];
    __shared__ float w1[C_], w2[C_];
    __shared__ float pd1[T_], pd2[T_];

    int bid = blockIdx.x;
    int tid = threadIdx.x;
    int wid = tid >> 5;
    int lane = tid & 31;

    w1[tid] = g_w1t[tid];
    w2[tid] = g_w2t[tid];
    if (tid < T_) { pd1[tid] = g_posd1[tid]; pd2[tid] = g_posd2[tid]; }

    int b = bid / J_, j = bid % J_;
    const float4* basev = g_srcT4 + ((size_t)b * J_ + j) * (T_ * 32);
    for (int i = tid; i < T_ * 32; i += 128) {
        xs4[(i >> 5) * (XS_STRIDE / 4) + (i & 31)] = basev[i];
    }
    __syncthreads();

    for (int n = wid; n < T_; n += 4) {
        float acc1 = 0.f, acc2 = 0.f;
        float4 xv4 = xs4[n * (XS_STRIDE / 4) + lane];
        const float* xv = (const float*)&xv4;
        #pragma unroll
        for (int k = 0; k < 4; ++k) {
            int c = 4 * lane + k;
            acc1 = fmaf(xv[k], w1[c], acc1);
            acc2 = fmaf(xv[k], w2[c], acc2);
        }
        #pragma unroll
        for (int off = 16; off > 0; off >>= 1) {
            acc1 += __shfl_xor_sync(0xffffffffu, acc1, off);
            acc2 += __shfl_xor_sync(0xffffffffu, acc2, off);
        }
        if (lane == 0) {
            s1[n] = acc1 + pd1[n];
            s2[n] = acc2 + pd2[n];
        }
    }
    __syncthreads();

    for (int i = tid; i < N_ * N_; i += 128) {
        int p = i / N_, q = i % N_;
        int k1 = 2 * p * N_ + 2 * q;
        int k2 = k1 + 1;
        int n1 = (k1 < N_ * N_) ? (k1 / N_) : ((k1 - N_ * N_) % N_);
        int n2 = (k2 < N_ * N_) ? (k2 / N_) : ((k2 - N_ * N_) % N_);
        float v = s1[n1] + s2[n2];
        ee[i] = (v >= 0.f) ? v : 0.2f * v;
    }
    __syncthreads();

    if (tid < N_) {
        int q = tid;
        float v[N_];
        float m = -3.402823466e38f;
        #pragma unroll
        for (int p = 0; p < N_; ++p) { v[p] = ee[p * N_ + q]; m = fmaxf(m, v[p]); }
        float s = 0.f;
        #pragma unroll
        for (int p = 0; p < N_; ++p) { v[p] = expf(v[p] - m); s += v[p]; }
        float inv = 1.f / s;
        float m2 = -3.402823466e38f;
        #pragma unroll
        for (int p = 0; p < N_; ++p) { v[p] *= inv; m2 = fmaxf(m2, v[p]); }
        float s2v = 0.f;
        #pragma unroll
        for (int p = 0; p < N_; ++p) { v[p] = expf(v[p] - m2); s2v += v[p]; }
        float inv2 = 1.f / s2v;
        float* o = out + (size_t)(NB_S + bid) * (N_ * N_);
        #pragma unroll
        for (int p = 0; p < N_; ++p) o[p * N_ + q] = v[p] * inv2;
    }
}

extern "C" void kernel_launch(void* const* d_in, const int* in_sizes, int n_in,
                              void* d_out, int out_size) {
    const float* src = (const float*)d_in[0];
    const float* Ws  = (const float*)d_in[1];
    const float* as_ = (const float*)d_in[2];
    const float* Wt  = (const float*)d_in[3];
    const float* at_ = (const float*)d_in[4];
    float* out = (float*)d_out;

    pre1_kernel<<<16 + T_, 128>>>(Ws, as_, Wt, at_);
    spatial_kernel<<<NB_S + 1, 128>>>(src, out);
    temporal_kernel<<<NB_T, 128>>>(out);
}

// round 5
// speedup vs baseline: 3.3034x; 1.0139x over previous
#include <cuda_runtime.h>
#include <math.h>

#define B_ 16
#define C_ 128
#define T_ 25
#define J_ 25
#define N_ 25
#define F_ 256
#define NB_S (B_*T_)   // 400 spatial blocks
#define NB_T (B_*J_)   // 400 temporal blocks
#define XS_STRIDE 132  // floats per smem row (128 + 4 pad, float4 compatible)

// Precomputed device-global scratch (static __device__ arrays: allowed)
__device__ float g_w1s[C_], g_w2s[C_], g_w1t[C_], g_w2t[C_];
__device__ float g_posd1[T_], g_posd2[T_];
__device__ float4 g_srcT4[B_ * J_ * T_ * (C_ / 4)];   // srcT[b][j][t][c], 5.12 MB

// ---------------------------------------------------------------------------
// K1: 16 blocks -> w vectors (warp-per-row, coalesced, butterfly reduce)
// ---------------------------------------------------------------------------
__global__ void __launch_bounds__(128) pre1_kernel(const float* __restrict__ Ws,
                                                   const float* __restrict__ as_,
                                                   const float* __restrict__ Wt,
                                                   const float* __restrict__ at_) {
    int bi = blockIdx.x;
    int tid = threadIdx.x;

    bool is_s = bi < 8;
    const float* W = is_s ? Ws : Wt;
    const float* a = is_s ? as_ : at_;
    float* o1 = is_s ? g_w1s : g_w1t;
    float* o2 = is_s ? g_w2s : g_w2t;
    int row0 = (bi & 7) * 16;

    int wid = tid >> 5;
    int lane = tid & 31;

    float a1v[8], a2v[8];
    #pragma unroll
    for (int u = 0; u < 8; ++u) {
        a1v[u] = __ldg(a + lane + 32 * u);
        a2v[u] = __ldg(a + F_ + lane + 32 * u);
    }

    #pragma unroll
    for (int k = 0; k < 4; ++k) {
        int row = row0 + wid * 4 + k;
        const float* Wrow = W + (size_t)row * F_;
        float acc1 = 0.f, acc2 = 0.f;
        #pragma unroll
        for (int u = 0; u < 8; ++u) {
            float wv = __ldg(Wrow + lane + 32 * u);
            acc1 = fmaf(wv, a1v[u], acc1);
            acc2 = fmaf(wv, a2v[u], acc2);
        }
        #pragma unroll
        for (int off = 16; off > 0; off >>= 1) {
            acc1 += __shfl_xor_sync(0xffffffffu, acc1, off);
            acc2 += __shfl_xor_sync(0xffffffffu, acc2, off);
        }
        if (lane == 0) { o1[row] = acc1; o2[row] = acc2; }
    }
}

// ---------------------------------------------------------------------------
// K2: blocks 0..399: spatial attention for (b,t) + transposed staging write
//     block  400   : posd constants — sinusoid table generated on the fly
//                    via square-and-multiply denom + angle-addition recurrence
// ---------------------------------------------------------------------------
__global__ void __launch_bounds__(128) spatial_kernel(const float* __restrict__ src,
                                                      float* __restrict__ out) {
    int bid = blockIdx.x;
    int tid = threadIdx.x;
    int wid = tid >> 5;
    int lane = tid & 31;

    if (bid == NB_S) {
        // posd[t] = sum_c (f32(pos_f64[t][c]) * 1000.0f) * w{1,2}t[c], fp64 acc.
        // Thread h2 owns channel pair (2h2: sin, 2h2+1: cos).
        __shared__ double sm1[T_][C_ / 2];
        __shared__ double sm2[T_][C_ / 2];
        if (tid < C_ / 2) {
            int h2 = tid;
            // denom = 10000^(h2/64) = 10^(h2/16), square-and-multiply.
            double denom = 1.0;
            if (h2 & 1)  denom *= 1.1547819846894583;   // 10^(1/16)
            if (h2 & 2)  denom *= 1.3335214321633240;   // 10^(1/8)
            if (h2 & 4)  denom *= 1.7782794100389228;   // 10^(1/4)
            if (h2 & 8)  denom *= 3.1622776601683795;   // 10^(1/2)
            if (h2 & 16) denom *= 10.0;
            if (h2 & 32) denom *= 100.0;
            double theta = 1.0 / denom;
            double S, Cc;
            sincos(theta, &S, &Cc);
            double w1a = (double)g_w1t[2 * h2], w1b = (double)g_w1t[2 * h2 + 1];
            double w2a = (double)g_w2t[2 * h2], w2b = (double)g_w2t[2 * h2 + 1];
            double s = 0.0, c = 1.0;                    // t = 0: sin=0, cos=1
            for (int t = 0; t < T_; ++t) {
                float sv = (float)s * 1000.0f;          // f32 cast, then *1000f
                float cv = (float)c * 1000.0f;
                sm1[t][h2] = (double)sv * w1a + (double)cv * w1b;
                sm2[t][h2] = (double)sv * w2a + (double)cv * w2b;
                double ns = s * Cc + c * S;             // angle-addition step
                double nc = c * Cc - s * S;
                s = ns; c = nc;
            }
        }
        __syncthreads();
        if (tid < 2 * T_) {
            int t = tid >> 1;
            const double* row = (tid & 1) ? sm2[t] : sm1[t];
            double a0 = 0.0, a1 = 0.0, a2 = 0.0, a3 = 0.0;
            #pragma unroll
            for (int k = 0; k < C_ / 2; k += 4) {
                a0 += row[k]; a1 += row[k + 1]; a2 += row[k + 2]; a3 += row[k + 3];
            }
            float r = (float)((a0 + a1) + (a2 + a3));
            if (tid & 1) g_posd2[t] = r; else g_posd1[t] = r;
        }
        return;
    }

    __shared__ float4 xs4[N_ * (XS_STRIDE / 4)];
    __shared__ float s1[N_], s2[N_];
    __shared__ float ee[N_ * N_];
    __shared__ float w1[C_], w2[C_];
    __shared__ float sumw1, sumw2;
    float* xs = (float*)xs4;

    int b = bid / T_, t = bid % T_;
    const float* base = src + (size_t)b * (C_ * T_ * J_) + t * J_;  // +c*625+j

    w1[tid] = g_w1s[tid];
    w2[tid] = g_w2s[tid];

    // gather x[j][c] (25-float contiguous runs along j)
    for (int i = tid; i < N_ * C_; i += 128) {
        int c = i / N_, n = i % N_;
        xs[n * XS_STRIDE + c] = __ldg(base + c * (T_ * J_) + n);
    }
    if (wid == 0) {   // sum of w vectors (for the spatial-PE scalar term)
        float v1 = w1[lane] + w1[lane + 32] + w1[lane + 64] + w1[lane + 96];
        float v2 = w2[lane] + w2[lane + 32] + w2[lane + 64] + w2[lane + 96];
        #pragma unroll
        for (int off = 16; off > 0; off >>= 1) {
            v1 += __shfl_xor_sync(0xffffffffu, v1, off);
            v2 += __shfl_xor_sync(0xffffffffu, v2, off);
        }
        if (lane == 0) { sumw1 = v1; sumw2 = v2; }
    }
    __syncthreads();

    // transposed staging write: srcT[b][j][t][c], coalesced 512B rows
    {
        float4* dst = g_srcT4 + ((size_t)b * J_) * (T_ * 32) + t * 32;
        for (int i = tid; i < N_ * 32; i += 128) {
            int j = i >> 5, c4 = i & 31;
            dst[(size_t)j * (T_ * 32) + c4] = xs4[j * (XS_STRIDE / 4) + c4];
        }
    }

    // warp-parallel per-node dots (+ PE distance to node 8)
    for (int n = wid; n < N_; n += 4) {
        float acc1 = 0.f, acc2 = 0.f, ss = 0.f;
        float4 xv4 = xs4[n * (XS_STRIDE / 4) + lane];
        float4 x84 = xs4[8 * (XS_STRIDE / 4) + lane];
        const float* xv = (const float*)&xv4;
        const float* x8 = (const float*)&x84;
        #pragma unroll
        for (int k = 0; k < 4; ++k) {
            int c = 4 * lane + k;
            acc1 = fmaf(xv[k], w1[c], acc1);
            acc2 = fmaf(xv[k], w2[c], acc2);
            float d = xv[k] - x8[k];
            ss = fmaf(d, d, ss);
        }
        #pragma unroll
        for (int off = 16; off > 0; off >>= 1) {
            acc1 += __shfl_xor_sync(0xffffffffu, acc1, off);
            acc2 += __shfl_xor_sync(0xffffffffu, acc2, off);
            ss   += __shfl_xor_sync(0xffffffffu, ss,   off);
        }
        if (lane == 0) {
            // c = ||(x - x8)/1000||; PE adds exp(-c) to every channel
            float delta = expf(-sqrtf(ss) * 0.001f);
            s1[n] = fmaf(delta, sumw1, acc1);
            s2[n] = fmaf(delta, sumw2, acc2);
        }
    }
    __syncthreads();

    // logits via reference's axis-1 concat index arithmetic + leaky relu
    for (int i = tid; i < N_ * N_; i += 128) {
        int p = i / N_, q = i % N_;
        int k1 = 2 * p * N_ + 2 * q;
        int k2 = k1 + 1;
        int n1 = (k1 < N_ * N_) ? (k1 / N_) : ((k1 - N_ * N_) % N_);
        int n2 = (k2 < N_ * N_) ? (k2 / N_) : ((k2 - N_ * N_) % N_);
        float v = s1[n1] + s2[n2];
        ee[i] = (v >= 0.f) ? v : 0.2f * v;
    }
    __syncthreads();

    // double softmax over p; one column q per thread
    if (tid < N_) {
        int q = tid;
        float v[N_];
        float m = -3.402823466e38f;
        #pragma unroll
        for (int p = 0; p < N_; ++p) { v[p] = ee[p * N_ + q]; m = fmaxf(m, v[p]); }
        float s = 0.f;
        #pragma unroll
        for (int p = 0; p < N_; ++p) { v[p] = expf(v[p] - m); s += v[p]; }
        float inv = 1.f / s;
        float m2 = -3.402823466e38f;
        #pragma unroll
        for (int p = 0; p < N_; ++p) { v[p] *= inv; m2 = fmaxf(m2, v[p]); }
        float s2v = 0.f;
        #pragma unroll
        for (int p = 0; p < N_; ++p) { v[p] = expf(v[p] - m2); s2v += v[p]; }
        float inv2 = 1.f / s2v;
        float* o = out + (size_t)bid * (N_ * N_);
        #pragma unroll
        for (int p = 0; p < N_; ++p) o[p * N_ + q] = v[p] * inv2;
    }
}

// ---------------------------------------------------------------------------
// K3: temporal attention for (b,j), reading the transposed staging tensor
//     with fully coalesced float4 loads.
// ---------------------------------------------------------------------------
__global__ void __launch_bounds__(128) temporal_kernel(float* __restrict__ out) {
    __shared__ float4 xs4[N_ * (XS_STRIDE / 4)];
    __shared__ float s1[N_], s2[N_];
    __shared__ float ee[N_ * N_];
    __shared__ float w1[C_], w2[C_];
    __shared__ float pd1[T_], pd2[T_];

    int bid = blockIdx.x;
    int tid = threadIdx.x;
    int wid = tid >> 5;
    int lane = tid & 31;

    w1[tid] = g_w1t[tid];
    w2[tid] = g_w2t[tid];
    if (tid < T_) { pd1[tid] = g_posd1[tid]; pd2[tid] = g_posd2[tid]; }

    int b = bid / J_, j = bid % J_;
    const float4* basev = g_srcT4 + ((size_t)b * J_ + j) * (T_ * 32);
    for (int i = tid; i < T_ * 32; i += 128) {
        xs4[(i >> 5) * (XS_STRIDE / 4) + (i & 31)] = basev[i];
    }
    __syncthreads();

    for (int n = wid; n < T_; n += 4) {
        float acc1 = 0.f, acc2 = 0.f;
        float4 xv4 = xs4[n * (XS_STRIDE / 4) + lane];
        const float* xv = (const float*)&xv4;
        #pragma unroll
        for (int k = 0; k < 4; ++k) {
            int c = 4 * lane + k;
            acc1 = fmaf(xv[k], w1[c], acc1);
            acc2 = fmaf(xv[k], w2[c], acc2);
        }
        #pragma unroll
        for (int off = 16; off > 0; off >>= 1) {
            acc1 += __shfl_xor_sync(0xffffffffu, acc1, off);
            acc2 += __shfl_xor_sync(0xffffffffu, acc2, off);
        }
        if (lane == 0) {
            s1[n] = acc1 + pd1[n];
            s2[n] = acc2 + pd2[n];
        }
    }
    __syncthreads();

    for (int i = tid; i < N_ * N_; i += 128) {
        int p = i / N_, q = i % N_;
        int k1 = 2 * p * N_ + 2 * q;
        int k2 = k1 + 1;
        int n1 = (k1 < N_ * N_) ? (k1 / N_) : ((k1 - N_ * N_) % N_);
        int n2 = (k2 < N_ * N_) ? (k2 / N_) : ((k2 - N_ * N_) % N_);
        float v = s1[n1] + s2[n2];
        ee[i] = (v >= 0.f) ? v : 0.2f * v;
    }
    __syncthreads();

    if (tid < N_) {
        int q = tid;
        float v[N_];
        float m = -3.402823466e38f;
        #pragma unroll
        for (int p = 0; p < N_; ++p) { v[p] = ee[p * N_ + q]; m = fmaxf(m, v[p]); }
        float s = 0.f;
        #pragma unroll
        for (int p = 0; p < N_; ++p) { v[p] = expf(v[p] - m); s += v[p]; }
        float inv = 1.f / s;
        float m2 = -3.402823466e38f;
        #pragma unroll
        for (int p = 0; p < N_; ++p) { v[p] *= inv; m2 = fmaxf(m2, v[p]); }
        float s2v = 0.f;
        #pragma unroll
        for (int p = 0; p < N_; ++p) { v[p] = expf(v[p] - m2); s2v += v[p]; }
        float inv2 = 1.f / s2v;
        float* o = out + (size_t)(NB_S + bid) * (N_ * N_);
        #pragma unroll
        for (int p = 0; p < N_; ++p) o[p * N_ + q] = v[p] * inv2;
    }
}

extern "C" void kernel_launch(void* const* d_in, const int* in_sizes, int n_in,
                              void* d_out, int out_size) {
    const float* src = (const float*)d_in[0];
    const float* Ws  = (const float*)d_in[1];
    const float* as_ = (const float*)d_in[2];
    const float* Wt  = (const float*)d_in[3];
    const float* at_ = (const float*)d_in[4];
    float* out = (float*)d_out;

    pre1_kernel<<<16, 128>>>(Ws, as_, Wt, at_);
    spatial_kernel<<<NB_S + 1, 128>>>(src, out);
    temporal_kernel<<<NB_T, 128>>>(out);
}

// round 6
// speedup vs baseline: 3.6047x; 1.0912x over previous
#include <cuda_runtime.h>
#include <math.h>

#define B_ 16
#define C_ 128
#define T_ 25
#define J_ 25
#define N_ 25
#define F_ 256
#define NB_S (B_*T_)   // 400 spatial blocks
#define NB_T (B_*J_)   // 400 temporal blocks
#define XS_STRIDE 132  // floats per smem row (128 + 4 pad, float4 compatible)
#define GRID_ (16 + 1 + NB_S + NB_T)   // 817

// Precomputed device-global scratch (static __device__ arrays: allowed)
__device__ float g_w1s[C_], g_w2s[C_], g_w1t[C_], g_w2t[C_];
__device__ float g_posd1[T_], g_posd2[T_];
__device__ float4 g_srcT4[B_ * J_ * T_ * (C_ / 4)];   // srcT[b][j][t][c], 5.12 MB

// Cross-block sync state (zero-initialized at load; last block resets -> each
// graph replay starts from zero).
__device__ int g_cnt_w = 0;      // -> 16 when all w vectors written
__device__ int g_cnt_stage = 0;  // -> 400 when staging tensor complete
__device__ int g_flag_posd = 0;  // -> 1 when posd constants written
__device__ int g_cnt_done = 0;   // completion counter for reset

__device__ __forceinline__ void spin_until(int* ctr, int target) {
    while (atomicAdd(ctr, 0) < target) { }
}

// ---------------------------------------------------------------------------
// ONE fused kernel. Roles by blockIdx.x:
//   0..15   : w = W@a halves (warp-per-row, coalesced, butterfly reduce)
//   16      : posd constants (on-the-fly fp64 sinusoid via recurrence)
//   17..416 : spatial attention (b,t) + transposed staging write
//   417..816: temporal attention (b,j) from staging
// All 817 blocks are co-resident (smem 17.4KB -> >=12 blk/SM, need 6), so
// atomic spin-waits cannot deadlock.
// ---------------------------------------------------------------------------
__global__ void __launch_bounds__(128) fused_kernel(const float* __restrict__ src,
                                                    const float* __restrict__ Ws,
                                                    const float* __restrict__ as_,
                                                    const float* __restrict__ Wt,
                                                    const float* __restrict__ at_,
                                                    float* __restrict__ out) {
    __shared__ float4 xs4[N_ * (XS_STRIDE / 4)];   // 13200 B (aliased by posd)
    __shared__ float s1[N_], s2[N_];
    __shared__ float ee[N_ * N_];
    __shared__ float w1[C_], w2[C_];
    __shared__ float sumw1, sumw2;

    int bid = blockIdx.x;
    int tid = threadIdx.x;
    int wid = tid >> 5;
    int lane = tid & 31;

    if (bid < 16) {
        // ------------------- W-dot blocks -------------------
        bool is_s = bid < 8;
        const float* W = is_s ? Ws : Wt;
        const float* a = is_s ? as_ : at_;
        float* o1 = is_s ? g_w1s : g_w1t;
        float* o2 = is_s ? g_w2s : g_w2t;
        int row0 = (bid & 7) * 16;

        float a1v[8], a2v[8];
        #pragma unroll
        for (int u = 0; u < 8; ++u) {
            a1v[u] = __ldg(a + lane + 32 * u);
            a2v[u] = __ldg(a + F_ + lane + 32 * u);
        }
        #pragma unroll
        for (int k = 0; k < 4; ++k) {
            int row = row0 + wid * 4 + k;
            const float* Wrow = W + (size_t)row * F_;
            float acc1 = 0.f, acc2 = 0.f;
            #pragma unroll
            for (int u = 0; u < 8; ++u) {
                float wv = __ldg(Wrow + lane + 32 * u);
                acc1 = fmaf(wv, a1v[u], acc1);
                acc2 = fmaf(wv, a2v[u], acc2);
            }
            #pragma unroll
            for (int off = 16; off > 0; off >>= 1) {
                acc1 += __shfl_xor_sync(0xffffffffu, acc1, off);
                acc2 += __shfl_xor_sync(0xffffffffu, acc2, off);
            }
            if (lane == 0) { o1[row] = acc1; o2[row] = acc2; }
        }
        __syncthreads();
        if (tid == 0) { __threadfence(); atomicAdd(&g_cnt_w, 1); }
    } else if (bid == 16) {
        // ------------------- posd block -------------------
        // posd[t] = sum_c (f32(pos_f64[t][c]) * 1000.0f) * w{1,2}t[c], fp64 acc.
        if (tid == 0) spin_until(&g_cnt_w, 16);
        __syncthreads();
        double* smd = (double*)xs4;    // [T_][64] doubles = 12800 B, aliased
        // denom = 10000^(h2/64) = 10^(h2/16) by square-and-multiply; one sincos
        // per h2; t-direction via angle-addition recurrence (err ~1e-15).
        double S = 0.0, Cc = 1.0, w_a = 0.0, w_b = 0.0;
        if (tid < C_ / 2) {
            int h2 = tid;
            double denom = 1.0;
            if (h2 & 1)  denom *= 1.1547819846894583;   // 10^(1/16)
            if (h2 & 2)  denom *= 1.3335214321633240;   // 10^(1/8)
            if (h2 & 4)  denom *= 1.7782794100389228;   // 10^(1/4)
            if (h2 & 8)  denom *= 3.1622776601683795;   // 10^(1/2)
            if (h2 & 16) denom *= 10.0;
            if (h2 & 32) denom *= 100.0;
            sincos(1.0 / denom, &S, &Cc);
        }
        #pragma unroll
        for (int v = 0; v < 2; ++v) {
            if (tid < C_ / 2) {
                int h2 = tid;
                const float* wv = v ? g_w2t : g_w1t;
                double wa = (double)wv[2 * h2], wb = (double)wv[2 * h2 + 1];
                double s = 0.0, c = 1.0;               // t=0: sin=0, cos=1
                for (int t = 0; t < T_; ++t) {
                    float sv = (float)s * 1000.0f;     // f32 cast, then *1000f
                    float cv = (float)c * 1000.0f;
                    smd[t * 64 + h2] = (double)sv * wa + (double)cv * wb;
                    double ns = s * Cc + c * S;
                    double nc = c * Cc - s * S;
                    s = ns; c = nc;
                }
            }
            __syncthreads();
            if (tid < T_) {
                const double* row = smd + tid * 64;
                double a0 = 0.0, a1 = 0.0, a2 = 0.0, a3 = 0.0;
                #pragma unroll
                for (int k = 0; k < 64; k += 4) {
                    a0 += row[k]; a1 += row[k+1]; a2 += row[k+2]; a3 += row[k+3];
                }
                float r = (float)((a0 + a1) + (a2 + a3));
                if (v) g_posd2[tid] = r; else g_posd1[tid] = r;
            }
            __syncthreads();
        }
        if (tid == 0) { __threadfence(); atomicAdd(&g_flag_posd, 1); }
        (void)w_a; (void)w_b;
    } else if (bid < 17 + NB_S) {
        // ------------------- spatial blocks -------------------
        int sb = bid - 17;
        int b = sb / T_, t = sb % T_;
        const float* base = src + (size_t)b * (C_ * T_ * J_) + t * J_;  // +c*625+j
        float* xs = (float*)xs4;

        // 1) independent work first: gather x[j][c] (25-float runs along j)
        for (int i = tid; i < N_ * C_; i += 128) {
            int c = i / N_, n = i % N_;
            xs[n * XS_STRIDE + c] = __ldg(base + c * (T_ * J_) + n);
        }
        __syncthreads();

        // 2) transposed staging write: srcT[b][j][t][c], coalesced 512B rows
        {
            float4* dst = g_srcT4 + ((size_t)b * J_) * (T_ * 32) + t * 32;
            for (int i = tid; i < N_ * 32; i += 128) {
                int j = i >> 5, c4 = i & 31;
                dst[(size_t)j * (T_ * 32) + c4] = xs4[j * (XS_STRIDE / 4) + c4];
            }
        }
        if (tid == 0) {
            __threadfence();
            atomicAdd(&g_cnt_stage, 1);
            // 3) now wait for the w vectors
            spin_until(&g_cnt_w, 16);
        }
        __syncthreads();

        w1[tid] = g_w1s[tid];
        w2[tid] = g_w2s[tid];
        __syncthreads();
        if (wid == 0) {   // sum of w vectors (for the spatial-PE scalar term)
            float v1 = w1[lane] + w1[lane+32] + w1[lane+64] + w1[lane+96];
            float v2 = w2[lane] + w2[lane+32] + w2[lane+64] + w2[lane+96];
            #pragma unroll
            for (int off = 16; off > 0; off >>= 1) {
                v1 += __shfl_xor_sync(0xffffffffu, v1, off);
                v2 += __shfl_xor_sync(0xffffffffu, v2, off);
            }
            if (lane == 0) { sumw1 = v1; sumw2 = v2; }
        }
        __syncthreads();

        // warp-parallel per-node dots (+ PE distance to node 8)
        for (int n = wid; n < N_; n += 4) {
            float acc1 = 0.f, acc2 = 0.f, ss = 0.f;
            float4 xv4 = xs4[n * (XS_STRIDE / 4) + lane];
            float4 x84 = xs4[8 * (XS_STRIDE / 4) + lane];
            const float* xv = (const float*)&xv4;
            const float* x8 = (const float*)&x84;
            #pragma unroll
            for (int k = 0; k < 4; ++k) {
                int c = 4 * lane + k;
                acc1 = fmaf(xv[k], w1[c], acc1);
                acc2 = fmaf(xv[k], w2[c], acc2);
                float d = xv[k] - x8[k];
                ss = fmaf(d, d, ss);
            }
            #pragma unroll
            for (int off = 16; off > 0; off >>= 1) {
                acc1 += __shfl_xor_sync(0xffffffffu, acc1, off);
                acc2 += __shfl_xor_sync(0xffffffffu, acc2, off);
                ss   += __shfl_xor_sync(0xffffffffu, ss,   off);
            }
            if (lane == 0) {
                float delta = expf(-sqrtf(ss) * 0.001f);
                s1[n] = fmaf(delta, sumw1, acc1);
                s2[n] = fmaf(delta, sumw2, acc2);
            }
        }
        __syncthreads();

        for (int i = tid; i < N_ * N_; i += 128) {
            int p = i / N_, q = i % N_;
            int k1 = 2 * p * N_ + 2 * q;
            int k2 = k1 + 1;
            int n1 = (k1 < N_*N_) ? (k1 / N_) : ((k1 - N_*N_) % N_);
            int n2 = (k2 < N_*N_) ? (k2 / N_) : ((k2 - N_*N_) % N_);
            float v = s1[n1] + s2[n2];
            ee[i] = (v >= 0.f) ? v : 0.2f * v;
        }
        __syncthreads();

        if (tid < N_) {
            int q = tid;
            float v[N_];
            float m = -3.402823466e38f;
            #pragma unroll
            for (int p = 0; p < N_; ++p) { v[p] = ee[p*N_+q]; m = fmaxf(m, v[p]); }
            float s = 0.f;
            #pragma unroll
            for (int p = 0; p < N_; ++p) { v[p] = expf(v[p] - m); s += v[p]; }
            float inv = 1.f / s;
            float m2 = -3.402823466e38f;
            #pragma unroll
            for (int p = 0; p < N_; ++p) { v[p] *= inv; m2 = fmaxf(m2, v[p]); }
            float s2v = 0.f;
            #pragma unroll
            for (int p = 0; p < N_; ++p) { v[p] = expf(v[p] - m2); s2v += v[p]; }
            float inv2 = 1.f / s2v;
            float* o = out + (size_t)sb * (N_ * N_);
            #pragma unroll
            for (int p = 0; p < N_; ++p) o[p * N_ + q] = v[p] * inv2;
        }
    } else {
        // ------------------- temporal blocks -------------------
        int tb = bid - (17 + NB_S);
        int b = tb / J_, j = tb % J_;

        __shared__ float pd1[T_], pd2[T_];
        if (tid == 0) {
            spin_until(&g_cnt_stage, NB_S);
            spin_until(&g_flag_posd, 1);
        }
        __syncthreads();

        w1[tid] = g_w1t[tid];
        w2[tid] = g_w2t[tid];
        if (tid < T_) { pd1[tid] = g_posd1[tid]; pd2[tid] = g_posd2[tid]; }

        const float4* basev = g_srcT4 + ((size_t)b * J_ + j) * (T_ * 32);
        for (int i = tid; i < T_ * 32; i += 128) {
            xs4[(i >> 5) * (XS_STRIDE / 4) + (i & 31)] = basev[i];
        }
        __syncthreads();

        for (int n = wid; n < T_; n += 4) {
            float acc1 = 0.f, acc2 = 0.f;
            float4 xv4 = xs4[n * (XS_STRIDE / 4) + lane];
            const float* xv = (const float*)&xv4;
            #pragma unroll
            for (int k = 0; k < 4; ++k) {
                int c = 4 * lane + k;
                acc1 = fmaf(xv[k], w1[c], acc1);
                acc2 = fmaf(xv[k], w2[c], acc2);
            }
            #pragma unroll
            for (int off = 16; off > 0; off >>= 1) {
                acc1 += __shfl_xor_sync(0xffffffffu, acc1, off);
                acc2 += __shfl_xor_sync(0xffffffffu, acc2, off);
            }
            if (lane == 0) {
                s1[n] = acc1 + pd1[n];
                s2[n] = acc2 + pd2[n];
            }
        }
        __syncthreads();

        for (int i = tid; i < N_ * N_; i += 128) {
            int p = i / N_, q = i % N_;
            int k1 = 2 * p * N_ + 2 * q;
            int k2 = k1 + 1;
            int n1 = (k1 < N_*N_) ? (k1 / N_) : ((k1 - N_*N_) % N_);
            int n2 = (k2 < N_*N_) ? (k2 / N_) : ((k2 - N_*N_) % N_);
            float v = s1[n1] + s2[n2];
            ee[i] = (v >= 0.f) ? v : 0.2f * v;
        }
        __syncthreads();

        if (tid < N_) {
            int q = tid;
            float v[N_];
            float m = -3.402823466e38f;
            #pragma unroll
            for (int p = 0; p < N_; ++p) { v[p] = ee[p*N_+q]; m = fmaxf(m, v[p]); }
            float s = 0.f;
            #pragma unroll
            for (int p = 0; p < N_; ++p) { v[p] = expf(v[p] - m); s += v[p]; }
            float inv = 1.f / s;
            float m2 = -3.402823466e38f;
            #pragma unroll
            for (int p = 0; p < N_; ++p) { v[p] *= inv; m2 = fmaxf(m2, v[p]); }
            float s2v = 0.f;
            #pragma unroll
            for (int p = 0; p < N_; ++p) { v[p] = expf(v[p] - m2); s2v += v[p]; }
            float inv2 = 1.f / s2v;
            float* o = out + (size_t)(NB_S + tb) * (N_ * N_);
            #pragma unroll
            for (int p = 0; p < N_; ++p) o[p * N_ + q] = v[p] * inv2;
        }
    }

    // -------- reset sync state for the next (graph-replayed) launch --------
    __syncthreads();
    if (tid == 0) {
        __threadfence();
        int d = atomicAdd(&g_cnt_done, 1);
        if (d == GRID_ - 1) {
            g_cnt_w = 0;
            g_cnt_stage = 0;
            g_flag_posd = 0;
            __threadfence();
            g_cnt_done = 0;
        }
    }
}

extern "C" void kernel_launch(void* const* d_in, const int* in_sizes, int n_in,
                              void* d_out, int out_size) {
    const float* src = (const float*)d_in[0];
    const float* Ws  = (const float*)d_in[1];
    const float* as_ = (const float*)d_in[2];
    const float* Wt  = (const float*)d_in[3];
    const float* at_ = (const float*)d_in[4];
    float* out = (float*)d_out;

    fused_kernel<<<GRID_, 128>>>(src, Ws, as_, Wt, at_, out);
}